// round 1
// baseline (speedup 1.0000x reference)
#include <cuda_runtime.h>
#include <float.h>
#include <math.h>
#include <stdint.h>

#define HW 16384
#define Dm 256
#define Bm 4

// ---------------- scratch (device globals: no allocations allowed) ----------
__device__ float g_x[Bm * Dm * HW];     // GEMM1 output (pre-BN)
__device__ float g_proj[Bm * Dm * HW];  // GEMM2 output (proj features)
__device__ float g_s[Dm];               // BN scale  = gamma * rsqrt(var+eps)
__device__ float g_c[Dm];               // BN shift  = beta - mean*scale
__device__ unsigned char g_m1[Bm * HW];
__device__ unsigned char g_m0[Bm * HW];
__device__ float g_mfg[Bm * Dm];        // masked sums (fg)
__device__ float g_mbg[Bm * Dm];        // masked sums (bg)
__device__ float g_bl[8];
__device__ int g_inc[8];

// ---------------- generic block reduction (256 threads) ---------------------
__device__ __forceinline__ float blk_sum(volatile float* scratch, float v, int tid) {
    int lane = tid & 31, w = tid >> 5;
#pragma unroll
    for (int off = 16; off; off >>= 1) v += __shfl_down_sync(0xffffffffu, v, off);
    if (lane == 0) scratch[w] = v;
    __syncthreads();
    if (w == 0) {
        v = (lane < 8) ? scratch[lane] : 0.f;
#pragma unroll
        for (int off = 4; off; off >>= 1) v += __shfl_down_sync(0xffffffffu, v, off);
        if (lane == 0) scratch[32] = v;
    }
    __syncthreads();
    return scratch[32];
}

// ---------------- masks ------------------------------------------------------
__global__ void k_masks(const float* __restrict__ prob_ori, const float* __restrict__ prob_aug,
                        const float* __restrict__ unc, const int* __restrict__ labels) {
    int idx = blockIdx.x * blockDim.x + threadIdx.x;
    if (idx >= Bm * HW) return;
    int b = idx >> 14;
    int hw = idx & (HW - 1);
    const float* po = prob_ori + (size_t)b * 2 * HW;
    const float* pa = prob_aug + (size_t)b * 2 * HW;
    int io = po[HW + hw] > po[hw];   // argmax over 2 classes (ties -> 0, like JAX)
    int ia = pa[HW + hw] > pa[hw];
    bool rel = (io == ia);
    bool diff = unc[idx] > 0.5f;
    int lab = labels[idx];
    bool valid = rel && diff;
    g_m1[idx] = (unsigned char)(valid && lab == 1);
    g_m0[idx] = (unsigned char)(valid && lab == 0);
}

// ---------------- tiled fp32 GEMM: C[e,n] = sum_d W[e,d]*A[d,n] + bias[e] ----
// APPLY=true: A = relu(bn(g_x)), C = g_proj.  APPLY=false: A = feat, C = g_x.
template <bool APPLY>
__global__ __launch_bounds__(256) void k_gemm(const float* __restrict__ Asrc,
                                              const float* __restrict__ Wm,
                                              const float* __restrict__ bias) {
    const int BK = 16;
    __shared__ __align__(16) float Ws[BK][128];
    __shared__ __align__(16) float As[BK][128];
    int nb = blockIdx.x * 128;
    int mb = blockIdx.y * 128;
    int bb = blockIdx.z;
    const float* Ab = (APPLY ? (const float*)g_x : Asrc) + (size_t)bb * Dm * HW;
    float* Cb = (APPLY ? g_proj : g_x) + (size_t)bb * Dm * HW;
    int tid = threadIdx.x;
    int tx = tid & 15, ty = tid >> 4;

    float acc[8][8];
#pragma unroll
    for (int i = 0; i < 8; i++)
#pragma unroll
        for (int j = 0; j < 8; j++) acc[i][j] = 0.f;

    for (int k0 = 0; k0 < Dm; k0 += BK) {
#pragma unroll
        for (int r = 0; r < 2; r++) {  // W tile 128x16
            int li = tid + r * 256;
            int m = li >> 2;
            int k4 = (li & 3) << 2;
            float4 w = *(const float4*)(Wm + (size_t)(mb + m) * Dm + k0 + k4);
            Ws[k4 + 0][m] = w.x;
            Ws[k4 + 1][m] = w.y;
            Ws[k4 + 2][m] = w.z;
            Ws[k4 + 3][m] = w.w;
        }
#pragma unroll
        for (int r = 0; r < 2; r++) {  // A tile 16x128
            int li = tid + r * 256;
            int k = li >> 5;
            int n4 = (li & 31) << 2;
            float4 a = *(const float4*)(Ab + (size_t)(k0 + k) * HW + nb + n4);
            if (APPLY) {
                int d = k0 + k;
                float s = g_s[d], c = g_c[d];
                a.x = fmaxf(fmaf(s, a.x, c), 0.f);
                a.y = fmaxf(fmaf(s, a.y, c), 0.f);
                a.z = fmaxf(fmaf(s, a.z, c), 0.f);
                a.w = fmaxf(fmaf(s, a.w, c), 0.f);
            }
            *(float4*)&As[k][n4] = a;
        }
        __syncthreads();
#pragma unroll
        for (int k = 0; k < BK; k++) {
            float rm[8], rn[8];
            *(float4*)rm = *(float4*)&Ws[k][ty * 8];
            *(float4*)(rm + 4) = *(float4*)&Ws[k][ty * 8 + 4];
            *(float4*)rn = *(float4*)&As[k][tx * 8];
            *(float4*)(rn + 4) = *(float4*)&As[k][tx * 8 + 4];
#pragma unroll
            for (int i = 0; i < 8; i++)
#pragma unroll
                for (int j = 0; j < 8; j++) acc[i][j] = fmaf(rm[i], rn[j], acc[i][j]);
        }
        __syncthreads();
    }
#pragma unroll
    for (int i = 0; i < 8; i++) {
        int e = mb + ty * 8 + i;
        float bv = bias[e];
        float4 o0 = make_float4(acc[i][0] + bv, acc[i][1] + bv, acc[i][2] + bv, acc[i][3] + bv);
        float4 o1 = make_float4(acc[i][4] + bv, acc[i][5] + bv, acc[i][6] + bv, acc[i][7] + bv);
        *(float4*)(Cb + (size_t)e * HW + nb + tx * 8) = o0;
        *(float4*)(Cb + (size_t)e * HW + nb + tx * 8 + 4) = o1;
    }
}

// ---------------- BN stats (training mode) ----------------------------------
__global__ __launch_bounds__(256) void k_stats(const float* __restrict__ gamma,
                                               const float* __restrict__ beta) {
    __shared__ float scratch[34];
    int e = blockIdx.x;
    int tid = threadIdx.x;
    float s = 0.f, sq = 0.f;
    for (int b = 0; b < Bm; b++) {
        const float* p = g_x + (size_t)b * Dm * HW + (size_t)e * HW;
        for (int i = tid; i < HW; i += 256) {
            float v = p[i];
            s += v;
            sq += v * v;
        }
    }
    float ts = blk_sum(scratch, s, tid);
    float tq = blk_sum(scratch, sq, tid);
    if (tid == 0) {
        const float inv_n = 1.f / (float)(Bm * HW);
        float mean = ts * inv_n;
        float var = fmaxf(tq * inv_n - mean * mean, 0.f);
        float sc = gamma[e] / sqrtf(var + 1e-5f);
        g_s[e] = sc;
        g_c[e] = beta[e] - mean * sc;
    }
}

// ---------------- masked prototype sums --------------------------------------
__global__ __launch_bounds__(256) void k_proto() {
    __shared__ float scratch[34];
    int e = blockIdx.x, b = blockIdx.y, tid = threadIdx.x;
    const float* p = g_proj + (size_t)b * Dm * HW + (size_t)e * HW;
    const unsigned char* m1 = g_m1 + b * HW;
    const unsigned char* m0 = g_m0 + b * HW;
    float sf = 0.f, sb = 0.f;
    for (int i = tid; i < HW; i += 256) {
        float v = p[i];
        if (m1[i]) sf += v;
        if (m0[i]) sb += v;
    }
    float tf = blk_sum(scratch, sf, tid);
    float tb = blk_sum(scratch, sb, tid);
    if (tid == 0) {
        g_mfg[b * Dm + e] = tf;
        g_mbg[b * Dm + e] = tb;
    }
}

// ---------------- pair loss ---------------------------------------------------
struct PairSmem {
    unsigned short listA[HW];
    unsigned short listN[HW];
    float qs[32 * 257];
    float rowbuf[256];
    float dotred[8 * 33];
    float red[34];
    int redi[34];
    float bestv;
    int besti;
    int cntA;
    int cntN;
    int aidx[32];
    float aflag[32];
    int cidx[128];
    float cflag[128];
    float cub[128];
    int pidx[64];
    float pflag[64];
    int nidx[64];
    float nflag[64];
    float pacc[32];
    float nacc[32];
};

__device__ __forceinline__ void pair_argmax(PairSmem* S, float v, int i, int tid) {
    int lane = tid & 31, w = tid >> 5;
#pragma unroll
    for (int off = 16; off; off >>= 1) {
        float ov = __shfl_down_sync(0xffffffffu, v, off);
        int oi = __shfl_down_sync(0xffffffffu, i, off);
        if (ov > v || (ov == v && oi < i)) { v = ov; i = oi; }
    }
    if (lane == 0) { S->red[w] = v; S->redi[w] = i; }
    __syncthreads();
    if (w == 0) {
        v = (lane < 8) ? S->red[lane] : -FLT_MAX;
        i = (lane < 8) ? S->redi[lane] : 0x7FFFFFFF;
#pragma unroll
        for (int off = 4; off; off >>= 1) {
            float ov = __shfl_down_sync(0xffffffffu, v, off);
            int oi = __shfl_down_sync(0xffffffffu, i, off);
            if (ov > v || (ov == v && oi < i)) { v = ov; i = oi; }
        }
        if (lane == 0) { S->bestv = v; S->besti = i; }
    }
    __syncthreads();
}

// strict (value desc, index asc) enumeration == JAX top_k order (tie-safe)
__device__ void select_topk(PairSmem* S, const unsigned short* list, int cnt,
                            const float* __restrict__ key, int K, int* oidx, float* oflag,
                            int tid) {
    float lastv = FLT_MAX;
    int lasti = -1;
    for (int kk = 0; kk < K; kk++) {
        float bv = -FLT_MAX;
        int bi = 0x7FFFFFFF;
        for (int ii = tid; ii < cnt; ii += 256) {
            int idx = list[ii];
            float v = key[idx];
            if (v < lastv || (v == lastv && idx > lasti)) {
                if (v > bv || (v == bv && idx < bi)) { bv = v; bi = idx; }
            }
        }
        pair_argmax(S, bv, bi, tid);
        float gbv = S->bestv;
        int gbi = S->besti;
        if (gbv > -FLT_MAX) {
            lastv = gbv;
            lasti = gbi;
            if (tid == 0) { oidx[kk] = gbi; oflag[kk] = 1.f; }
        } else {
            lastv = -FLT_MAX;
            lasti = 0x7FFFFFFF;
            if (tid == 0) { oidx[kk] = 0; oflag[kk] = 0.f; }
        }
        __syncthreads();
    }
}

// top-64 by uncertainty among 128 candidates (invalid -> -1e30 like JAX NEG)
__device__ void select_hard(PairSmem* S, const float* __restrict__ unc_b, int* oidx,
                            float* oflag, int tid) {
    if (tid < 128) S->cub[tid] = (S->cflag[tid] != 0.f) ? unc_b[S->cidx[tid]] : -1e30f;
    __syncthreads();
    float lastv = FLT_MAX;
    int lasti = -1;
    for (int kk = 0; kk < 64; kk++) {
        float bv = -FLT_MAX;
        int bi = 0x7FFFFFFF;
        if (tid < 128) {
            float v = S->cub[tid];
            if (v < lastv || (v == lastv && tid > lasti)) { bv = v; bi = tid; }
        }
        pair_argmax(S, bv, bi, tid);
        int bj = S->besti;
        if (tid == 0) {
            oidx[kk] = S->cidx[bj];
            oflag[kk] = S->cflag[bj];
        }
        lastv = S->bestv;
        lasti = bj;
        __syncthreads();
    }
}

__global__ __launch_bounds__(256) void k_pair(const float* __restrict__ unc,
                                              const float* __restrict__ r_anc,
                                              const float* __restrict__ r_pos,
                                              const float* __restrict__ r_neg) {
    extern __shared__ char smraw[];
    PairSmem* S = (PairSmem*)smraw;
    int task = blockIdx.x;
    int b = task >> 1, c = task & 1;
    int tid = threadIdx.x;
    const unsigned char* am = (c == 0 ? g_m1 : g_m0) + b * HW;
    const unsigned char* nm = (c == 0 ? g_m0 : g_m1) + b * HW;

    if (tid == 0) { S->cntA = 0; S->cntN = 0; }
    __syncthreads();
    for (int i = tid; i < HW; i += 256) {
        if (am[i]) { int p = atomicAdd(&S->cntA, 1); S->listA[p] = (unsigned short)i; }
        if (nm[i]) { int p = atomicAdd(&S->cntN, 1); S->listN[p] = (unsigned short)i; }
    }
    __syncthreads();
    int cntA = S->cntA, cntN = S->cntN;

    const float* ra = r_anc + ((size_t)b * 2 + c) * HW;
    const float* rp = r_pos + ((size_t)b * 2 + c) * HW;
    const float* rn = r_neg + ((size_t)b * 2 + c) * HW;
    const float* ub = unc + (size_t)b * HW;

    select_topk(S, S->listA, cntA, ra, 32, S->aidx, S->aflag, tid);
    select_topk(S, S->listA, cntA, rp, 128, S->cidx, S->cflag, tid);
    select_hard(S, ub, S->pidx, S->pflag, tid);
    select_topk(S, S->listN, cntN, rn, 128, S->cidx, S->cflag, tid);
    select_hard(S, ub, S->nidx, S->nflag, tid);

    if (tid < 32) { S->pacc[tid] = 0.f; S->nacc[tid] = 0.f; }
    __syncthreads();

    const float* projb = g_proj + (size_t)b * Dm * HW;
    // stage normalized anchors (padded stride 257: bank-conflict free)
    for (int a = 0; a < 32; a++) {
        float v = projb[(size_t)tid * HW + S->aidx[a]];
        float ss = blk_sum(S->red, v * v, tid);
        float sc = 1.f / fmaxf(sqrtf(ss), 1e-12f);
        S->qs[a * 257 + tid] = v * sc;
    }
    __syncthreads();

    int w = tid >> 5, l = tid & 31;
    for (int pass = 0; pass < 2; pass++) {
        const int* sidx = pass == 0 ? S->pidx : S->nidx;
        const float* sflag = pass == 0 ? S->pflag : S->nflag;
        float* accp = pass == 0 ? S->pacc : S->nacc;
        for (int s = 0; s < 64; s++) {
            if (sflag[s] == 0.f) continue;  // uniform (smem broadcast)
            float v = projb[(size_t)tid * HW + sidx[s]];
            float ss = blk_sum(S->red, v * v, tid);
            float sc = 1.f / fmaxf(sqrtf(ss), 1e-12f);
            S->rowbuf[tid] = v * sc;
            __syncthreads();
            float part = 0.f;
#pragma unroll
            for (int ii = 0; ii < 32; ii++)
                part = fmaf(S->qs[l * 257 + w * 32 + ii], S->rowbuf[w * 32 + ii], part);
            S->dotred[w * 33 + l] = part;
            __syncthreads();
            if (w == 0) {
                float dot = 0.f;
#pragma unroll
                for (int jj = 0; jj < 8; jj++) dot += S->dotred[jj * 33 + l];
                accp[l] += expf(dot * 10.f);  // 1/TAU = 10
            }
            __syncthreads();
        }
    }

    if (w == 0) {
        bool inc = (cntA >= 1) && (cntN >= 1);
        float p = S->pacc[l], n = S->nacc[l];
        if (!inc) p += 1.f;
        float per = -logf(p / (p + n + 1e-8f));
        float af = S->aflag[l];
        float ws = per * af, as = af;
#pragma unroll
        for (int off = 16; off; off >>= 1) {
            ws += __shfl_down_sync(0xffffffffu, ws, off);
            as += __shfl_down_sync(0xffffffffu, as, off);
        }
        if (l == 0) {
            float bl = ws / fmaxf(as, 1.f);
            g_bl[task] = inc ? bl : 0.f;
            g_inc[task] = inc ? 1 : 0;
        }
    }
}

// ---------------- final: local + global loss ---------------------------------
__global__ __launch_bounds__(256) void k_final(float* __restrict__ out, int out_size) {
    __shared__ float scratch[34];
    __shared__ float qf[4][257], qb[4][257];
    __shared__ float cf[4], cb[4];
    __shared__ float pfv[4], pbv[4], nfv[4], nbv[4];
    int tid = threadIdx.x;

    for (int b = 0; b < 4; b++) {
        float c1 = 0.f, c0 = 0.f;
        for (int i = tid; i < HW; i += 256) {
            c1 += (float)g_m1[b * HW + i];
            c0 += (float)g_m0[b * HW + i];
        }
        float s1 = blk_sum(scratch, c1, tid);
        float s0 = blk_sum(scratch, c0, tid);
        if (tid == 0) { cf[b] = s1; cb[b] = s0; }
    }
    __syncthreads();

    for (int b = 0; b < 4; b++) {
        float mf = g_mfg[b * Dm + tid] / fmaxf(cf[b], 1.f);
        float mb_ = g_mbg[b * Dm + tid] / fmaxf(cb[b], 1.f);
        float ssf = blk_sum(scratch, mf * mf, tid);
        qf[b][tid] = mf / fmaxf(sqrtf(ssf), 1e-12f);
        float ssb = blk_sum(scratch, mb_ * mb_, tid);
        qb[b][tid] = mb_ / fmaxf(sqrtf(ssb), 1e-12f);
    }
    __syncthreads();

    for (int b = 0; b < 4; b++) {
        float d1 = blk_sum(scratch, qf[b][tid] * qf[b][tid], tid);
        float d2 = blk_sum(scratch, qb[b][tid] * qb[b][tid], tid);
        if (tid == 0) {
            pfv[b] = expf(d1 * 10.f);
            pbv[b] = expf(d2 * 10.f);
            nfv[b] = 0.f;
            nbv[b] = 0.f;
        }
        __syncthreads();
    }
    for (int b = 0; b < 4; b++) {
        for (int j = 0; j <= b; j++) {
            float dqbqf = blk_sum(scratch, qb[j][tid] * qf[b][tid], tid);
            float dqfqb = blk_sum(scratch, qf[j][tid] * qb[b][tid], tid);
            if (tid == 0) {
                bool vgj = (cf[j] >= 1.f) && (cb[j] >= 1.f);
                if (vgj) {
                    nfv[b] += expf(dqbqf * 10.f);
                    nbv[b] += expf(dqfqb * 10.f);
                }
            }
            __syncthreads();
        }
    }

    if (tid == 0) {
        float lsum = 0.f;
        int icnt = 0;
        for (int t = 0; t < 8; t++) {
            lsum += g_bl[t];
            icnt += g_inc[t];
        }
        float l_local = lsum / (float)max(icnt, 1);
        float gs = 0.f;
        int vcnt = 0;
        for (int b = 0; b < 4; b++) {
            bool vg = (cf[b] >= 1.f) && (cb[b] >= 1.f);
            if (vg) {
                float lg = -logf(pfv[b] / (pfv[b] + nfv[b] + 1e-8f)) -
                           logf(pbv[b] / (pbv[b] + nbv[b] + 1e-8f));
                gs += lg;
                vcnt++;
            }
        }
        float l_global = gs / (float)max(vcnt, 1);
        if (out_size > 0) out[0] = l_local + 0.5f * l_global;
        if (out_size > 1) out[1] = l_local;
        if (out_size > 2) out[2] = l_global;
    }
}

// ---------------- launch ------------------------------------------------------
extern "C" void kernel_launch(void* const* d_in, const int* in_sizes, int n_in, void* d_out,
                              int out_size) {
    const float* feat = (const float*)d_in[0];
    const int* labels = (const int*)d_in[1];
    const float* prob_ori = (const float*)d_in[2];
    const float* prob_aug = (const float*)d_in[3];
    const float* unc = (const float*)d_in[4];
    const float* r_anc = (const float*)d_in[5];
    const float* r_pos = (const float*)d_in[6];
    const float* r_neg = (const float*)d_in[7];
    const float* w1 = (const float*)d_in[8];
    const float* b1 = (const float*)d_in[9];
    const float* gamma = (const float*)d_in[10];
    const float* beta = (const float*)d_in[11];
    const float* w2 = (const float*)d_in[12];
    const float* b2 = (const float*)d_in[13];

    cudaFuncSetAttribute(k_pair, cudaFuncAttributeMaxDynamicSharedMemorySize,
                         (int)sizeof(PairSmem));

    k_masks<<<(Bm * HW + 255) / 256, 256>>>(prob_ori, prob_aug, unc, labels);
    dim3 gg(HW / 128, Dm / 128, Bm);
    k_gemm<false><<<gg, 256>>>(feat, w1, b1);
    k_stats<<<Dm, 256>>>(gamma, beta);
    k_gemm<true><<<gg, 256>>>(nullptr, w2, b2);
    k_proto<<<dim3(Dm, Bm), 256>>>();
    k_pair<<<8, 256, sizeof(PairSmem)>>>(unc, r_anc, r_pos, r_neg);
    k_final<<<1, 256>>>((float*)d_out, out_size);
}

// round 2
// speedup vs baseline: 2.6503x; 2.6503x over previous
#include <cuda_runtime.h>
#include <float.h>
#include <math.h>
#include <stdint.h>

#define HW 16384
#define Dm 256
#define Bm 4
#define NBLK 128  // HW/128 n-blocks per (m,b)

// ---------------- scratch (device globals: no allocations allowed) ----------
__device__ float g_x[Bm * Dm * HW];     // GEMM1 output (pre-BN)
__device__ float g_proj[Bm * Dm * HW];  // GEMM2 output (proj features)
__device__ float g_s[Dm];               // BN scale  = gamma * rsqrt(var+eps)
__device__ float g_c[Dm];               // BN shift  = beta - mean*scale
__device__ unsigned char g_m1[Bm * HW];
__device__ unsigned char g_m0[Bm * HW];
__device__ float g_ps[Dm * 512];        // stats partial sums  [e][b*128+nblk]
__device__ float g_pq[Dm * 512];        // stats partial sumsq
__device__ float g_pfg[Bm * Dm * NBLK]; // proto partials fg
__device__ float g_pbg[Bm * Dm * NBLK]; // proto partials bg
__device__ float g_mfg[Bm * Dm];
__device__ float g_mbg[Bm * Dm];
__device__ float g_bl[8];
__device__ int g_inc[8];

// ---------------- generic block reduction (256 threads) ---------------------
__device__ __forceinline__ float blk_sum(volatile float* scratch, float v, int tid) {
    int lane = tid & 31, w = tid >> 5;
#pragma unroll
    for (int off = 16; off; off >>= 1) v += __shfl_down_sync(0xffffffffu, v, off);
    if (lane == 0) scratch[w] = v;
    __syncthreads();
    if (w == 0) {
        v = (lane < 8) ? scratch[lane] : 0.f;
#pragma unroll
        for (int off = 4; off; off >>= 1) v += __shfl_down_sync(0xffffffffu, v, off);
        if (lane == 0) scratch[32] = v;
    }
    __syncthreads();
    return scratch[32];
}

// ---------------- masks ------------------------------------------------------
__global__ void k_masks(const float* __restrict__ prob_ori, const float* __restrict__ prob_aug,
                        const float* __restrict__ unc, const int* __restrict__ labels) {
    int idx = blockIdx.x * blockDim.x + threadIdx.x;
    if (idx >= Bm * HW) return;
    int b = idx >> 14;
    int hw = idx & (HW - 1);
    const float* po = prob_ori + (size_t)b * 2 * HW;
    const float* pa = prob_aug + (size_t)b * 2 * HW;
    int io = po[HW + hw] > po[hw];
    int ia = pa[HW + hw] > pa[hw];
    bool rel = (io == ia);
    bool diff = unc[idx] > 0.5f;
    int lab = labels[idx];
    bool valid = rel && diff;
    g_m1[idx] = (unsigned char)(valid && lab == 1);
    g_m0[idx] = (unsigned char)(valid && lab == 0);
}

// ---------------- double-buffered fp32 GEMM + fused reductions ---------------
// C[e,n] = sum_d W[e,d]*A[d,n] + bias[e]
// APPLY=false: A=feat, C=g_x, epilogue emits BN-stat partials.
// APPLY=true:  A=relu(bn(g_x)), C=g_proj, epilogue emits masked proto partials.
template <bool APPLY>
__global__ __launch_bounds__(256, 2) void k_gemm(const float* __restrict__ Asrc,
                                                 const float* __restrict__ Wm,
                                                 const float* __restrict__ bias) {
    __shared__ __align__(16) float Ws[2][16][128];
    __shared__ __align__(16) float As[2][16][128];
    const int nb = blockIdx.x * 128, mb = blockIdx.y * 128, bb = blockIdx.z;
    const float* Ab = (APPLY ? (const float*)g_x : Asrc) + (size_t)bb * Dm * HW;
    float* Cb = (APPLY ? g_proj : g_x) + (size_t)bb * Dm * HW;
    const int tid = threadIdx.x;
    const int tx = tid & 15, ty = tid >> 4;
    const int wm0 = tid >> 2, wk0 = (tid & 3) << 2;
    const int ak0 = tid >> 5, an0 = (tid & 31) << 2;

    float4 wv0, wv1, av0, av1;

#define GLOAD(k0)                                                                    \
    {                                                                                \
        wv0 = *(const float4*)(Wm + (size_t)(mb + wm0) * Dm + (k0) + wk0);           \
        wv1 = *(const float4*)(Wm + (size_t)(mb + wm0 + 64) * Dm + (k0) + wk0);      \
        av0 = *(const float4*)(Ab + (size_t)((k0) + ak0) * HW + nb + an0);           \
        av1 = *(const float4*)(Ab + (size_t)((k0) + ak0 + 8) * HW + nb + an0);       \
        if (APPLY) {                                                                 \
            float s0 = g_s[(k0) + ak0], c0 = g_c[(k0) + ak0];                        \
            float s1 = g_s[(k0) + ak0 + 8], c1 = g_c[(k0) + ak0 + 8];                \
            av0.x = fmaxf(fmaf(s0, av0.x, c0), 0.f);                                 \
            av0.y = fmaxf(fmaf(s0, av0.y, c0), 0.f);                                 \
            av0.z = fmaxf(fmaf(s0, av0.z, c0), 0.f);                                 \
            av0.w = fmaxf(fmaf(s0, av0.w, c0), 0.f);                                 \
            av1.x = fmaxf(fmaf(s1, av1.x, c1), 0.f);                                 \
            av1.y = fmaxf(fmaf(s1, av1.y, c1), 0.f);                                 \
            av1.z = fmaxf(fmaf(s1, av1.z, c1), 0.f);                                 \
            av1.w = fmaxf(fmaf(s1, av1.w, c1), 0.f);                                 \
        }                                                                            \
    }
#define SSTORE(bf)                                                                   \
    {                                                                                \
        Ws[bf][wk0 + 0][wm0] = wv0.x;                                                \
        Ws[bf][wk0 + 1][wm0] = wv0.y;                                                \
        Ws[bf][wk0 + 2][wm0] = wv0.z;                                                \
        Ws[bf][wk0 + 3][wm0] = wv0.w;                                                \
        Ws[bf][wk0 + 0][wm0 + 64] = wv1.x;                                           \
        Ws[bf][wk0 + 1][wm0 + 64] = wv1.y;                                           \
        Ws[bf][wk0 + 2][wm0 + 64] = wv1.z;                                           \
        Ws[bf][wk0 + 3][wm0 + 64] = wv1.w;                                           \
        *(float4*)&As[bf][ak0][an0] = av0;                                           \
        *(float4*)&As[bf][ak0 + 8][an0] = av1;                                       \
    }

    float acc[8][8];
#pragma unroll
    for (int i = 0; i < 8; i++)
#pragma unroll
        for (int j = 0; j < 8; j++) acc[i][j] = 0.f;

    GLOAD(0);
    SSTORE(0);
    __syncthreads();
    int buf = 0;

#pragma unroll 1
    for (int kt = 0; kt < 16; kt++) {
        if (kt < 15) GLOAD((kt + 1) * 16);
        float rA[2][8], rB[2][8];
        *(float4*)&rA[0][0] = *(float4*)&Ws[buf][0][ty * 8];
        *(float4*)&rA[0][4] = *(float4*)&Ws[buf][0][ty * 8 + 4];
        *(float4*)&rB[0][0] = *(float4*)&As[buf][0][tx * 8];
        *(float4*)&rB[0][4] = *(float4*)&As[buf][0][tx * 8 + 4];
#pragma unroll
        for (int k = 0; k < 16; k++) {
            int cur = k & 1;
            if (k < 15) {
                *(float4*)&rA[cur ^ 1][0] = *(float4*)&Ws[buf][k + 1][ty * 8];
                *(float4*)&rA[cur ^ 1][4] = *(float4*)&Ws[buf][k + 1][ty * 8 + 4];
                *(float4*)&rB[cur ^ 1][0] = *(float4*)&As[buf][k + 1][tx * 8];
                *(float4*)&rB[cur ^ 1][4] = *(float4*)&As[buf][k + 1][tx * 8 + 4];
            }
#pragma unroll
            for (int i = 0; i < 8; i++)
#pragma unroll
                for (int j = 0; j < 8; j++) acc[i][j] = fmaf(rA[cur][i], rB[cur][j], acc[i][j]);
        }
        if (kt < 15) {
            SSTORE(buf ^ 1);
            __syncthreads();
            buf ^= 1;
        }
    }
#undef GLOAD
#undef SSTORE

    if (!APPLY) {
#pragma unroll
        for (int i = 0; i < 8; i++) {
            int e = mb + ty * 8 + i;
            float bv = bias[e];
            float o[8];
            float rs = 0.f, rq = 0.f;
#pragma unroll
            for (int j = 0; j < 8; j++) {
                o[j] = acc[i][j] + bv;
                rs += o[j];
                rq = fmaf(o[j], o[j], rq);
            }
            *(float4*)(Cb + (size_t)e * HW + nb + tx * 8) = *(float4*)&o[0];
            *(float4*)(Cb + (size_t)e * HW + nb + tx * 8 + 4) = *(float4*)&o[4];
#pragma unroll
            for (int off = 8; off; off >>= 1) {
                rs += __shfl_down_sync(0xffffffffu, rs, off, 16);
                rq += __shfl_down_sync(0xffffffffu, rq, off, 16);
            }
            if (tx == 0) {
                int slot = e * 512 + bb * NBLK + blockIdx.x;
                g_ps[slot] = rs;
                g_pq[slot] = rq;
            }
        }
    } else {
        unsigned char mv1[8], mv0[8];
#pragma unroll
        for (int j = 0; j < 8; j++) {
            mv1[j] = g_m1[bb * HW + nb + tx * 8 + j];
            mv0[j] = g_m0[bb * HW + nb + tx * 8 + j];
        }
#pragma unroll
        for (int i = 0; i < 8; i++) {
            int e = mb + ty * 8 + i;
            float bv = bias[e];
            float o[8];
            float fg = 0.f, bg = 0.f;
#pragma unroll
            for (int j = 0; j < 8; j++) {
                o[j] = acc[i][j] + bv;
                if (mv1[j]) fg += o[j];
                if (mv0[j]) bg += o[j];
            }
            *(float4*)(Cb + (size_t)e * HW + nb + tx * 8) = *(float4*)&o[0];
            *(float4*)(Cb + (size_t)e * HW + nb + tx * 8 + 4) = *(float4*)&o[4];
#pragma unroll
            for (int off = 8; off; off >>= 1) {
                fg += __shfl_down_sync(0xffffffffu, fg, off, 16);
                bg += __shfl_down_sync(0xffffffffu, bg, off, 16);
            }
            if (tx == 0) {
                int slot = (bb * Dm + e) * NBLK + blockIdx.x;
                g_pfg[slot] = fg;
                g_pbg[slot] = bg;
            }
        }
    }
}

// ---------------- finalize BN stats ------------------------------------------
__global__ __launch_bounds__(128) void k_finstats(const float* __restrict__ gamma,
                                                  const float* __restrict__ beta) {
    __shared__ float shs[4], shq[4];
    int e = blockIdx.x, t = threadIdx.x, lane = t & 31, wp = t >> 5;
    float s = 0.f, q = 0.f;
    for (int i = t; i < 512; i += 128) {
        s += g_ps[e * 512 + i];
        q += g_pq[e * 512 + i];
    }
#pragma unroll
    for (int off = 16; off; off >>= 1) {
        s += __shfl_down_sync(0xffffffffu, s, off);
        q += __shfl_down_sync(0xffffffffu, q, off);
    }
    if (lane == 0) {
        shs[wp] = s;
        shq[wp] = q;
    }
    __syncthreads();
    if (t == 0) {
        float ts = shs[0] + shs[1] + shs[2] + shs[3];
        float tq = shq[0] + shq[1] + shq[2] + shq[3];
        const float inv_n = 1.f / (float)(Bm * HW);
        float mean = ts * inv_n;
        float var = fmaxf(tq * inv_n - mean * mean, 0.f);
        float sc = gamma[e] / sqrtf(var + 1e-5f);
        g_s[e] = sc;
        g_c[e] = beta[e] - mean * sc;
    }
}

// ---------------- finalize prototypes ----------------------------------------
__global__ __launch_bounds__(128) void k_finproto() {
    __shared__ float shf[4], shb[4];
    int e = blockIdx.x, b = blockIdx.y, t = threadIdx.x, lane = t & 31, wp = t >> 5;
    float f = g_pfg[(b * Dm + e) * NBLK + t];
    float g = g_pbg[(b * Dm + e) * NBLK + t];
#pragma unroll
    for (int off = 16; off; off >>= 1) {
        f += __shfl_down_sync(0xffffffffu, f, off);
        g += __shfl_down_sync(0xffffffffu, g, off);
    }
    if (lane == 0) {
        shf[wp] = f;
        shb[wp] = g;
    }
    __syncthreads();
    if (t == 0) {
        g_mfg[b * Dm + e] = shf[0] + shf[1] + shf[2] + shf[3];
        g_mbg[b * Dm + e] = shb[0] + shb[1] + shb[2] + shb[3];
    }
}

// ---------------- pair loss ---------------------------------------------------
struct PairSmem {
    unsigned short listA[HW];
    unsigned short listN[HW];
    unsigned long long sbuf[4096];
    float qs[32 * 257];
    float vbuf[8][264];
    int hist[256];
    float red[34];
    int redi[34];
    float warpP[8][33];
    float warpN[8][33];
    int aidx[32];
    float aflag[32];
    int cidx[128];
    float cflag[128];
    int pidx[64];
    float pflag[64];
    int nidx[64];
    float nflag[64];
    int cntA, cntN, coll, bstar;
    float bestv;
    int besti;
};

__device__ __forceinline__ void pair_argmax(PairSmem* S, float v, int i, int tid) {
    int lane = tid & 31, w = tid >> 5;
#pragma unroll
    for (int off = 16; off; off >>= 1) {
        float ov = __shfl_down_sync(0xffffffffu, v, off);
        int oi = __shfl_down_sync(0xffffffffu, i, off);
        if (ov > v || (ov == v && oi < i)) { v = ov; i = oi; }
    }
    if (lane == 0) { S->red[w] = v; S->redi[w] = i; }
    __syncthreads();
    if (w == 0) {
        v = (lane < 8) ? S->red[lane] : -FLT_MAX;
        i = (lane < 8) ? S->redi[lane] : 0x7FFFFFFF;
#pragma unroll
        for (int off = 4; off; off >>= 1) {
            float ov = __shfl_down_sync(0xffffffffu, v, off);
            int oi = __shfl_down_sync(0xffffffffu, i, off);
            if (ov > v || (ov == v && oi < i)) { v = ov; i = oi; }
        }
        if (lane == 0) { S->bestv = v; S->besti = i; }
    }
    __syncthreads();
}

// fallback: strict (value desc, index asc) enumeration (tie-exact)
__device__ void select_topk(PairSmem* S, const unsigned short* list, int cnt,
                            const float* __restrict__ key, int K, int* oidx, float* oflag,
                            int tid) {
    float lastv = FLT_MAX;
    int lasti = -1;
    for (int kk = 0; kk < K; kk++) {
        float bv = -FLT_MAX;
        int bi = 0x7FFFFFFF;
        for (int ii = tid; ii < cnt; ii += 256) {
            int idx = list[ii];
            float v = key[idx];
            if (v < lastv || (v == lastv && idx > lasti)) {
                if (v > bv || (v == bv && idx < bi)) { bv = v; bi = idx; }
            }
        }
        pair_argmax(S, bv, bi, tid);
        float gbv = S->bestv;
        int gbi = S->besti;
        if (gbv > -FLT_MAX) {
            lastv = gbv;
            lasti = gbi;
            if (tid == 0) { oidx[kk] = gbi; oflag[kk] = 1.f; }
        } else {
            lastv = -FLT_MAX;
            lasti = 0x7FFFFFFF;
            if (tid == 0) { oidx[kk] = 0; oflag[kk] = 0.f; }
        }
        __syncthreads();
    }
}

__device__ void bitonic_desc(PairSmem* S, int n, int tid) {
    for (int k = 2; k <= n; k <<= 1)
        for (int j = k >> 1; j > 0; j >>= 1) {
            for (int t = tid; t < n; t += 256) {
                int ixj = t ^ j;
                if (ixj > t) {
                    unsigned long long x = S->sbuf[t], y = S->sbuf[ixj];
                    bool desc = ((t & k) == 0);
                    if (desc ? (x < y) : (x > y)) {
                        S->sbuf[t] = y;
                        S->sbuf[ixj] = x;
                    }
                }
            }
            __syncthreads();
        }
}

// histogram-threshold select: exact JAX top_k (value desc, idx asc) semantics
__device__ void radix_select(PairSmem* S, const unsigned short* list, int cnt,
                             const float* __restrict__ key, int K, int* oidx, float* oflag,
                             int tid) {
    int target = min(K, cnt);
    if (target == 0) {
        for (int kk = tid; kk < K; kk += 256) { oidx[kk] = 0; oflag[kk] = 0.f; }
        __syncthreads();
        return;
    }
    S->hist[tid] = 0;
    if (tid < 256) {}  // blockDim==256: one bin each
    __syncthreads();
    for (int ii = tid; ii < cnt; ii += 256) {
        float r = key[list[ii]];
        int b = (int)(r * 256.f);
        b = b < 0 ? 0 : (b > 255 ? 255 : b);
        atomicAdd(&S->hist[b], 1);
    }
    __syncthreads();
    if (tid == 0) {
        int acc = 0, bs = 0;
        for (int b = 255; b >= 0; b--) {
            acc += S->hist[b];
            if (acc >= target) { bs = b; break; }
        }
        S->bstar = bs;
        S->coll = 0;
    }
    __syncthreads();
    int bstar = S->bstar;
    for (int ii = tid; ii < cnt; ii += 256) {
        int idx = list[ii];
        float r = key[idx];
        int b = (int)(r * 256.f);
        b = b < 0 ? 0 : (b > 255 ? 255 : b);
        if (b >= bstar) {
            int p = atomicAdd(&S->coll, 1);
            if (p < 4096)
                S->sbuf[p] = ((unsigned long long)__float_as_uint(r) << 32) |
                             (unsigned long long)(unsigned int)(~(unsigned int)idx);
        }
    }
    __syncthreads();
    int coll = S->coll;
    if (coll > 4096) {  // degenerate distribution: exact fallback
        select_topk(S, list, cnt, key, K, oidx, oflag, tid);
        return;
    }
    int n = 1;
    while (n < coll) n <<= 1;
    for (int i = coll + tid; i < n; i += 256) S->sbuf[i] = 0ull;
    __syncthreads();
    bitonic_desc(S, n, tid);
    for (int kk = tid; kk < K; kk += 256) {
        if (kk < target) {
            oidx[kk] = (int)(~(unsigned int)(S->sbuf[kk] & 0xFFFFFFFFull));
            oflag[kk] = 1.f;
        } else {
            oidx[kk] = 0;
            oflag[kk] = 0.f;
        }
    }
    __syncthreads();
}

// top-64 by uncertainty among 128 candidates (position-asc tiebreak, invalid last)
__device__ void hard_select(PairSmem* S, const float* __restrict__ ub, int* oidx, float* oflag,
                            int tid) {
    if (tid < 128) {
        unsigned long long kv;
        if (S->cflag[tid] != 0.f) {
            unsigned int u = __float_as_uint(ub[S->cidx[tid]]) + 1u;
            kv = ((unsigned long long)u << 32) |
                 (unsigned long long)(unsigned int)(~(unsigned int)tid);
        } else {
            kv = (unsigned long long)(unsigned int)(~(unsigned int)tid);
        }
        S->sbuf[tid] = kv;
    }
    __syncthreads();
    bitonic_desc(S, 128, tid);
    if (tid < 64) {
        int t = (int)((~(unsigned int)(S->sbuf[tid] & 0xFFFFFFFFull)) & 127u);
        oidx[tid] = S->cidx[t];
        oflag[tid] = S->cflag[t];
    }
    __syncthreads();
}

__global__ __launch_bounds__(256) void k_pair(const float* __restrict__ unc,
                                              const float* __restrict__ r_anc,
                                              const float* __restrict__ r_pos,
                                              const float* __restrict__ r_neg) {
    extern __shared__ char smraw[];
    PairSmem* S = (PairSmem*)smraw;
    int task = blockIdx.x;
    int b = task >> 1, c = task & 1;
    int tid = threadIdx.x, w = tid >> 5, l = tid & 31;
    const unsigned char* am = (c == 0 ? g_m1 : g_m0) + b * HW;
    const unsigned char* nm = (c == 0 ? g_m0 : g_m1) + b * HW;

    if (tid == 0) { S->cntA = 0; S->cntN = 0; }
    __syncthreads();
    for (int i = tid; i < HW; i += 256) {
        if (am[i]) { int p = atomicAdd(&S->cntA, 1); S->listA[p] = (unsigned short)i; }
        if (nm[i]) { int p = atomicAdd(&S->cntN, 1); S->listN[p] = (unsigned short)i; }
    }
    __syncthreads();
    int cntA = S->cntA, cntN = S->cntN;

    const float* ra = r_anc + ((size_t)b * 2 + c) * HW;
    const float* rp = r_pos + ((size_t)b * 2 + c) * HW;
    const float* rn = r_neg + ((size_t)b * 2 + c) * HW;
    const float* ub = unc + (size_t)b * HW;

    radix_select(S, S->listA, cntA, ra, 32, S->aidx, S->aflag, tid);
    radix_select(S, S->listA, cntA, rp, 128, S->cidx, S->cflag, tid);
    hard_select(S, ub, S->pidx, S->pflag, tid);
    radix_select(S, S->listN, cntN, rn, 128, S->cidx, S->cflag, tid);
    hard_select(S, ub, S->nidx, S->nflag, tid);

    const float* projb = g_proj + (size_t)b * Dm * HW;

    // stage normalized anchors: warp w handles anchors 4w..4w+3 (no block barriers)
    for (int q = 0; q < 4; q++) {
        int a = w * 4 + q;
        int idx = S->aidx[a];
        float v[8], ss = 0.f;
#pragma unroll
        for (int cc = 0; cc < 8; cc++) {
            v[cc] = projb[(size_t)(l + 32 * cc) * HW + idx];
            ss = fmaf(v[cc], v[cc], ss);
        }
#pragma unroll
        for (int off = 16; off; off >>= 1) ss += __shfl_xor_sync(0xffffffffu, ss, off);
        float sc = 1.f / fmaxf(sqrtf(ss), 1e-12f);
#pragma unroll
        for (int cc = 0; cc < 8; cc++) S->qs[a * 257 + l + 32 * cc] = v[cc] * sc;
    }
    __syncthreads();

    // samples: warp w handles s = w, w+8, ... ; lane = anchor
    float accP = 0.f, accN = 0.f;
    for (int s = w; s < 128; s += 8) {
        int si = s & 63;
        bool isP = s < 64;
        float fl = isP ? S->pflag[si] : S->nflag[si];
        if (fl != 0.f) {
            int idx = isP ? S->pidx[si] : S->nidx[si];
            float v[8], ss = 0.f;
#pragma unroll
            for (int cc = 0; cc < 8; cc++) {
                v[cc] = projb[(size_t)(l + 32 * cc) * HW + idx];
                ss = fmaf(v[cc], v[cc], ss);
            }
#pragma unroll
            for (int off = 16; off; off >>= 1) ss += __shfl_xor_sync(0xffffffffu, ss, off);
            float sc = 1.f / fmaxf(sqrtf(ss), 1e-12f);
#pragma unroll
            for (int cc = 0; cc < 8; cc++) S->vbuf[w][l + 32 * cc] = v[cc] * sc;
            __syncwarp();
            float dot = 0.f;
            const float* qrow = &S->qs[l * 257];
#pragma unroll 8
            for (int d = 0; d < 256; d++) dot = fmaf(qrow[d], S->vbuf[w][d], dot);
            float ev = expf(dot * 10.f);  // 1/TAU
            if (isP) accP += ev; else accN += ev;
            __syncwarp();
        }
    }
    S->warpP[w][l] = accP;
    S->warpN[w][l] = accN;
    __syncthreads();

    if (w == 0) {
        float p = 0.f, n = 0.f;
#pragma unroll
        for (int ww = 0; ww < 8; ww++) {
            p += S->warpP[ww][l];
            n += S->warpN[ww][l];
        }
        bool inc = (cntA >= 1) && (cntN >= 1);
        if (!inc) p += 1.f;
        float per = -logf(p / (p + n + 1e-8f));
        float af = S->aflag[l];
        float ws = per * af, as = af;
#pragma unroll
        for (int off = 16; off; off >>= 1) {
            ws += __shfl_down_sync(0xffffffffu, ws, off);
            as += __shfl_down_sync(0xffffffffu, as, off);
        }
        if (l == 0) {
            g_bl[task] = inc ? (ws / fmaxf(as, 1.f)) : 0.f;
            g_inc[task] = inc ? 1 : 0;
        }
    }
}

// ---------------- final: local + global loss ---------------------------------
__global__ __launch_bounds__(256) void k_final(float* __restrict__ out, int out_size) {
    __shared__ float scratch[34];
    __shared__ float qf[4][257], qb[4][257];
    __shared__ float cf[4], cb[4];
    __shared__ float pfv[4], pbv[4], nfv[4], nbv[4];
    int tid = threadIdx.x;

    for (int b = 0; b < 4; b++) {
        float c1 = 0.f, c0 = 0.f;
        for (int i = tid; i < HW; i += 256) {
            c1 += (float)g_m1[b * HW + i];
            c0 += (float)g_m0[b * HW + i];
        }
        float s1 = blk_sum(scratch, c1, tid);
        float s0 = blk_sum(scratch, c0, tid);
        if (tid == 0) { cf[b] = s1; cb[b] = s0; }
    }
    __syncthreads();

    for (int b = 0; b < 4; b++) {
        float mf = g_mfg[b * Dm + tid] / fmaxf(cf[b], 1.f);
        float mb_ = g_mbg[b * Dm + tid] / fmaxf(cb[b], 1.f);
        float ssf = blk_sum(scratch, mf * mf, tid);
        qf[b][tid] = mf / fmaxf(sqrtf(ssf), 1e-12f);
        float ssb = blk_sum(scratch, mb_ * mb_, tid);
        qb[b][tid] = mb_ / fmaxf(sqrtf(ssb), 1e-12f);
    }
    __syncthreads();

    for (int b = 0; b < 4; b++) {
        float d1 = blk_sum(scratch, qf[b][tid] * qf[b][tid], tid);
        float d2 = blk_sum(scratch, qb[b][tid] * qb[b][tid], tid);
        if (tid == 0) {
            pfv[b] = expf(d1 * 10.f);
            pbv[b] = expf(d2 * 10.f);
            nfv[b] = 0.f;
            nbv[b] = 0.f;
        }
        __syncthreads();
    }
    for (int b = 0; b < 4; b++) {
        for (int j = 0; j <= b; j++) {
            float dqbqf = blk_sum(scratch, qb[j][tid] * qf[b][tid], tid);
            float dqfqb = blk_sum(scratch, qf[j][tid] * qb[b][tid], tid);
            if (tid == 0) {
                bool vgj = (cf[j] >= 1.f) && (cb[j] >= 1.f);
                if (vgj) {
                    nfv[b] += expf(dqbqf * 10.f);
                    nbv[b] += expf(dqfqb * 10.f);
                }
            }
            __syncthreads();
        }
    }

    if (tid == 0) {
        float lsum = 0.f;
        int icnt = 0;
        for (int t = 0; t < 8; t++) {
            lsum += g_bl[t];
            icnt += g_inc[t];
        }
        float l_local = lsum / (float)max(icnt, 1);
        float gs = 0.f;
        int vcnt = 0;
        for (int b = 0; b < 4; b++) {
            bool vg = (cf[b] >= 1.f) && (cb[b] >= 1.f);
            if (vg) {
                float lg = -logf(pfv[b] / (pfv[b] + nfv[b] + 1e-8f)) -
                           logf(pbv[b] / (pbv[b] + nbv[b] + 1e-8f));
                gs += lg;
                vcnt++;
            }
        }
        float l_global = gs / (float)max(vcnt, 1);
        if (out_size > 0) out[0] = l_local + 0.5f * l_global;
        if (out_size > 1) out[1] = l_local;
        if (out_size > 2) out[2] = l_global;
    }
}

// ---------------- launch ------------------------------------------------------
extern "C" void kernel_launch(void* const* d_in, const int* in_sizes, int n_in, void* d_out,
                              int out_size) {
    const float* feat = (const float*)d_in[0];
    const int* labels = (const int*)d_in[1];
    const float* prob_ori = (const float*)d_in[2];
    const float* prob_aug = (const float*)d_in[3];
    const float* unc = (const float*)d_in[4];
    const float* r_anc = (const float*)d_in[5];
    const float* r_pos = (const float*)d_in[6];
    const float* r_neg = (const float*)d_in[7];
    const float* w1 = (const float*)d_in[8];
    const float* b1 = (const float*)d_in[9];
    const float* gamma = (const float*)d_in[10];
    const float* beta = (const float*)d_in[11];
    const float* w2 = (const float*)d_in[12];
    const float* b2 = (const float*)d_in[13];

    cudaFuncSetAttribute(k_pair, cudaFuncAttributeMaxDynamicSharedMemorySize,
                         (int)sizeof(PairSmem));

    k_masks<<<(Bm * HW + 255) / 256, 256>>>(prob_ori, prob_aug, unc, labels);
    dim3 gg(HW / 128, Dm / 128, Bm);
    k_gemm<false><<<gg, 256>>>(feat, w1, b1);
    k_finstats<<<Dm, 128>>>(gamma, beta);
    k_gemm<true><<<gg, 256>>>(nullptr, w2, b2);
    k_finproto<<<dim3(Dm, Bm), 128>>>();
    k_pair<<<8, 256, sizeof(PairSmem)>>>(unc, r_anc, r_pos, r_neg);
    k_final<<<1, 256>>>((float*)d_out, out_size);
}

// round 4
// speedup vs baseline: 4.2484x; 1.6030x over previous
#include <cuda_runtime.h>
#include <cuda_bf16.h>
#include <float.h>
#include <math.h>
#include <stdint.h>

#define HW 16384
#define Dm 256
#define Bm 4
#define NBLK 128

// ---------------- scratch ----------------------------------------------------
__device__ float g_x[Bm * HW * Dm];     // GEMM1 output, layout [b][n][d]
__device__ float g_proj[Bm * HW * Dm];  // GEMM2 output, layout [b][n][e]
__device__ float g_s[Dm];
__device__ float g_c[Dm];
__device__ unsigned char g_m1[Bm * HW];
__device__ unsigned char g_m0[Bm * HW];
__device__ float g_ps[Dm * 512];
__device__ float g_pq[Dm * 512];
__device__ float g_pfg[Bm * Dm * NBLK];
__device__ float g_pbg[Bm * Dm * NBLK];
__device__ float g_mfg[Bm * Dm];
__device__ float g_mbg[Bm * Dm];
__device__ float g_bl[8];
__device__ int g_inc[8];

// ---------------- block reduction --------------------------------------------
__device__ __forceinline__ float blk_sum(volatile float* scratch, float v, int tid) {
    int lane = tid & 31, w = tid >> 5;
#pragma unroll
    for (int off = 16; off; off >>= 1) v += __shfl_down_sync(0xffffffffu, v, off);
    if (lane == 0) scratch[w] = v;
    __syncthreads();
    if (w == 0) {
        v = (lane < 8) ? scratch[lane] : 0.f;
#pragma unroll
        for (int off = 4; off; off >>= 1) v += __shfl_down_sync(0xffffffffu, v, off);
        if (lane == 0) scratch[32] = v;
    }
    __syncthreads();
    return scratch[32];
}

// ---------------- masks ------------------------------------------------------
__global__ void k_masks(const float* __restrict__ prob_ori, const float* __restrict__ prob_aug,
                        const float* __restrict__ unc, const int* __restrict__ labels) {
    int idx = blockIdx.x * blockDim.x + threadIdx.x;
    if (idx >= Bm * HW) return;
    int b = idx >> 14;
    int hw = idx & (HW - 1);
    const float* po = prob_ori + (size_t)b * 2 * HW;
    const float* pa = prob_aug + (size_t)b * 2 * HW;
    int io = po[HW + hw] > po[hw];
    int ia = pa[HW + hw] > pa[hw];
    bool rel = (io == ia);
    bool diff = unc[idx] > 0.5f;
    int lab = labels[idx];
    bool valid = rel && diff;
    g_m1[idx] = (unsigned char)(valid && lab == 1);
    g_m0[idx] = (unsigned char)(valid && lab == 0);
}

// ---------------- bf16 hi/lo split -------------------------------------------
__device__ __forceinline__ void split2(float a, float b, uint32_t& h, uint32_t& l) {
    __nv_bfloat16 ah = __float2bfloat16_rn(a), bh = __float2bfloat16_rn(b);
    float ar = a - __bfloat162float(ah), br = b - __bfloat162float(bh);
    __nv_bfloat16 al = __float2bfloat16_rn(ar), bl = __float2bfloat16_rn(br);
    h = (uint32_t)*(unsigned short*)&ah | ((uint32_t)*(unsigned short*)&bh << 16);
    l = (uint32_t)*(unsigned short*)&al | ((uint32_t)*(unsigned short*)&bl << 16);
}

__device__ __forceinline__ void mma16816(float* c, const uint32_t* a, uint32_t b0, uint32_t b1) {
    asm volatile(
        "mma.sync.aligned.m16n8k16.row.col.f32.bf16.bf16.f32 "
        "{%0,%1,%2,%3}, {%4,%5,%6,%7}, {%8,%9}, {%0,%1,%2,%3};"
        : "+f"(c[0]), "+f"(c[1]), "+f"(c[2]), "+f"(c[3])
        : "r"(a[0]), "r"(a[1]), "r"(a[2]), "r"(a[3]), "r"(b0), "r"(b1));
}

// ---------------- HMMA GEMM: C[e,n] = sum_d A[e,d]*B[n,d] + bias[e] ----------
// APPLY=false: B = feat[b][d][n] (transposed load), C -> g_x[b][n][e], BN partials.
// APPLY=true:  B = relu(bn(g_x[b][n][d])), C -> g_proj[b][n][e], proto partials.
// smem tiles: [128 rows][72 halves] padded (row stride 36 words) -> conflict-free frags.
#define ROWW 36                      // words per padded row
#define MATW (128 * ROWW)            // words per matrix (4608)
#define SMEM_WORDS (4 * MATW)        // Ah, Al, Bh, Bl
#define GEMM_SMEM (SMEM_WORDS * 4 + 8192)

template <bool APPLY>
__global__ __launch_bounds__(256, 2) void k_gemm_mma(const float* __restrict__ Asrc,
                                                     const float* __restrict__ Wm,
                                                     const float* __restrict__ bias) {
    extern __shared__ __align__(16) char smraw[];
    uint32_t* Ah = (uint32_t*)smraw;
    uint32_t* Al = Ah + MATW;
    uint32_t* Bh = Al + MATW;
    uint32_t* Bl = Bh + MATW;
    float* fext = (float*)(Bl + MATW);
    float* m1f = fext;            // [128]
    float* m0f = fext + 128;      // [128]
    float* scs = fext + 256;      // [256]
    float* scc = fext + 512;      // [256]
    float* bsm = fext + 768;      // [128]
    float* red = fext + 896;      // [2][128][4]

    const int tid = threadIdx.x, lane = tid & 31, wid = tid >> 5;
    const int warp_m = wid >> 2, warp_n = wid & 3;
    const int bx = blockIdx.x, mb = blockIdx.y, bb = blockIdx.z;
    const int nb = bx * 128;

    if (tid < 128) bsm[tid] = bias[mb * 128 + tid];
    if (APPLY) {
        scs[tid] = g_s[tid];
        scc[tid] = g_c[tid];
        if (tid < 128) {
            m1f[tid] = (float)g_m1[bb * HW + nb + tid];
            m0f[tid] = (float)g_m0[bb * HW + nb + tid];
        }
    }

    const float* Wbase = Wm + (size_t)(mb * 128) * 256;
    const float* featb = Asrc + (size_t)bb * Dm * HW;  // [d][n]
    const float* gxb = g_x + (size_t)bb * HW * 256;    // [n][d]

    float acc[4][4][4];
#pragma unroll
    for (int i = 0; i < 4; i++)
#pragma unroll
        for (int j = 0; j < 4; j++)
#pragma unroll
            for (int k = 0; k < 4; k++) acc[i][j][k] = 0.f;

    const int rA = lane >> 2, cA = lane & 3;

#pragma unroll 1
    for (int kc = 0; kc < 4; kc++) {
        const int d0 = kc * 64;
        __syncthreads();
        // ---- A (weights 128x64) ----
#pragma unroll
        for (int it = 0; it < 4; it++) {
            int lin = tid + it * 256;
            int row = lin >> 3, k8 = (lin & 7) << 3;
            const float* s = Wbase + (size_t)row * 256 + d0 + k8;
            float4 a0 = *(const float4*)s, a1 = *(const float4*)(s + 4);
            uint32_t H[4], L[4];
            split2(a0.x, a0.y, H[0], L[0]);
            split2(a0.z, a0.w, H[1], L[1]);
            split2(a1.x, a1.y, H[2], L[2]);
            split2(a1.z, a1.w, H[3], L[3]);
            int off = row * ROWW + (k8 >> 1);
            *(uint4*)&Ah[off] = make_uint4(H[0], H[1], H[2], H[3]);
            *(uint4*)&Al[off] = make_uint4(L[0], L[1], L[2], L[3]);
        }
        // ---- B (activations 128x64) ----
        if (!APPLY) {
#pragma unroll
            for (int it = 0; it < 4; it++) {
                int lin = tid + it * 256;
                int n_l = lin & 127, k8 = (lin >> 7) << 3;
                const float* s = featb + (size_t)(d0 + k8) * HW + nb + n_l;
                float v[8];
#pragma unroll
                for (int j = 0; j < 8; j++) v[j] = s[(size_t)j * HW];
                uint32_t H[4], L[4];
#pragma unroll
                for (int j = 0; j < 4; j++) split2(v[2 * j], v[2 * j + 1], H[j], L[j]);
                int off = n_l * ROWW + (k8 >> 1);
                *(uint4*)&Bh[off] = make_uint4(H[0], H[1], H[2], H[3]);
                *(uint4*)&Bl[off] = make_uint4(L[0], L[1], L[2], L[3]);
            }
        } else {
#pragma unroll
            for (int it = 0; it < 4; it++) {
                int lin = tid + it * 256;
                int row = lin >> 3, k8 = (lin & 7) << 3;
                const float* s = gxb + (size_t)(nb + row) * 256 + d0 + k8;
                float4 a0 = *(const float4*)s, a1 = *(const float4*)(s + 4);
                float v[8] = {a0.x, a0.y, a0.z, a0.w, a1.x, a1.y, a1.z, a1.w};
#pragma unroll
                for (int j = 0; j < 8; j++) {
                    int d = d0 + k8 + j;
                    v[j] = fmaxf(fmaf(scs[d], v[j], scc[d]), 0.f);
                }
                uint32_t H[4], L[4];
#pragma unroll
                for (int j = 0; j < 4; j++) split2(v[2 * j], v[2 * j + 1], H[j], L[j]);
                int off = row * ROWW + (k8 >> 1);
                *(uint4*)&Bh[off] = make_uint4(H[0], H[1], H[2], H[3]);
                *(uint4*)&Bl[off] = make_uint4(L[0], L[1], L[2], L[3]);
            }
        }
        __syncthreads();

#pragma unroll
        for (int kt = 0; kt < 4; kt++) {
            uint32_t Afh[4][4], Afl[4][4];
#pragma unroll
            for (int mt = 0; mt < 4; mt++) {
                int base = (warp_m * 64 + mt * 16 + rA) * ROWW + kt * 8 + cA;
                Afh[mt][0] = Ah[base];
                Afh[mt][1] = Ah[base + 8 * ROWW];
                Afh[mt][2] = Ah[base + 4];
                Afh[mt][3] = Ah[base + 8 * ROWW + 4];
                Afl[mt][0] = Al[base];
                Afl[mt][1] = Al[base + 8 * ROWW];
                Afl[mt][2] = Al[base + 4];
                Afl[mt][3] = Al[base + 8 * ROWW + 4];
            }
#pragma unroll
            for (int nt = 0; nt < 4; nt++) {
                int bbase = (warp_n * 32 + nt * 8 + rA) * ROWW + kt * 8 + cA;
                uint32_t bh0 = Bh[bbase], bh1 = Bh[bbase + 4];
                uint32_t bl0 = Bl[bbase], bl1 = Bl[bbase + 4];
#pragma unroll
                for (int mt = 0; mt < 4; mt++) {
                    mma16816(acc[mt][nt], Afh[mt], bh0, bh1);
                    mma16816(acc[mt][nt], Afh[mt], bl0, bl1);
                    mma16816(acc[mt][nt], Afl[mt], bh0, bh1);
                }
            }
        }
    }

    // ---- epilogue ----
    __syncthreads();
    float* outb = (APPLY ? g_proj : g_x) + (size_t)bb * HW * 256;
#pragma unroll
    for (int mt = 0; mt < 4; mt++) {
#pragma unroll
        for (int h = 0; h < 2; h++) {
            int e_local = warp_m * 64 + mt * 16 + rA + h * 8;
            int e = mb * 128 + e_local;
            float bv = bsm[e_local];
            float s0 = 0.f, s1 = 0.f;
#pragma unroll
            for (int nt = 0; nt < 4; nt++) {
                int nc = warp_n * 32 + nt * 8 + cA * 2;
                float v0 = acc[mt][nt][h * 2 + 0] + bv;
                float v1 = acc[mt][nt][h * 2 + 1] + bv;
                outb[(size_t)(nb + nc) * 256 + e] = v0;
                outb[(size_t)(nb + nc + 1) * 256 + e] = v1;
                if (!APPLY) {
                    s0 += v0 + v1;
                    s1 += v0 * v0 + v1 * v1;
                } else {
                    s0 += m1f[nc] * v0 + m1f[nc + 1] * v1;
                    s1 += m0f[nc] * v0 + m0f[nc + 1] * v1;
                }
            }
            s0 += __shfl_down_sync(0xffffffffu, s0, 1, 4);
            s0 += __shfl_down_sync(0xffffffffu, s0, 2, 4);
            s1 += __shfl_down_sync(0xffffffffu, s1, 1, 4);
            s1 += __shfl_down_sync(0xffffffffu, s1, 2, 4);
            if (cA == 0) {
                red[(0 * 128 + e_local) * 4 + warp_n] = s0;
                red[(1 * 128 + e_local) * 4 + warp_n] = s1;
            }
        }
    }
    __syncthreads();
    {
        int q = tid >> 7, e_local = tid & 127;
        int e = mb * 128 + e_local;
        const float* r4 = &red[(q * 128 + e_local) * 4];
        float s = r4[0] + r4[1] + r4[2] + r4[3];
        if (!APPLY) {
            if (q == 0)
                g_ps[(size_t)e * 512 + bb * 128 + bx] = s;
            else
                g_pq[(size_t)e * 512 + bb * 128 + bx] = s;
        } else {
            if (q == 0)
                g_pfg[(size_t)(bb * Dm + e) * NBLK + bx] = s;
            else
                g_pbg[(size_t)(bb * Dm + e) * NBLK + bx] = s;
        }
    }
}

// ---------------- finalize BN stats ------------------------------------------
__global__ __launch_bounds__(128) void k_finstats(const float* __restrict__ gamma,
                                                  const float* __restrict__ beta) {
    __shared__ float shs[4], shq[4];
    int e = blockIdx.x, t = threadIdx.x, lane = t & 31, wp = t >> 5;
    float s = 0.f, q = 0.f;
    for (int i = t; i < 512; i += 128) {
        s += g_ps[e * 512 + i];
        q += g_pq[e * 512 + i];
    }
#pragma unroll
    for (int off = 16; off; off >>= 1) {
        s += __shfl_down_sync(0xffffffffu, s, off);
        q += __shfl_down_sync(0xffffffffu, q, off);
    }
    if (lane == 0) {
        shs[wp] = s;
        shq[wp] = q;
    }
    __syncthreads();
    if (t == 0) {
        float ts = shs[0] + shs[1] + shs[2] + shs[3];
        float tq = shq[0] + shq[1] + shq[2] + shq[3];
        const float inv_n = 1.f / (float)(Bm * HW);
        float mean = ts * inv_n;
        float var = fmaxf(tq * inv_n - mean * mean, 0.f);
        float sc = gamma[e] / sqrtf(var + 1e-5f);
        g_s[e] = sc;
        g_c[e] = beta[e] - mean * sc;
    }
}

// ---------------- finalize prototypes ----------------------------------------
__global__ __launch_bounds__(128) void k_finproto() {
    __shared__ float shf[4], shb[4];
    int e = blockIdx.x, b = blockIdx.y, t = threadIdx.x, lane = t & 31, wp = t >> 5;
    float f = g_pfg[(b * Dm + e) * NBLK + t];
    float g = g_pbg[(b * Dm + e) * NBLK + t];
#pragma unroll
    for (int off = 16; off; off >>= 1) {
        f += __shfl_down_sync(0xffffffffu, f, off);
        g += __shfl_down_sync(0xffffffffu, g, off);
    }
    if (lane == 0) {
        shf[wp] = f;
        shb[wp] = g;
    }
    __syncthreads();
    if (t == 0) {
        g_mfg[b * Dm + e] = shf[0] + shf[1] + shf[2] + shf[3];
        g_mbg[b * Dm + e] = shb[0] + shb[1] + shb[2] + shb[3];
    }
}

// ---------------- pair loss ---------------------------------------------------
struct PairSmem {
    unsigned short listA[HW];
    unsigned short listN[HW];
    unsigned long long sbuf[4096];
    float qs[32 * 257];
    float vbuf[8][264];
    int hist[256];
    float red[34];
    int redi[34];
    float warpP[8][33];
    float warpN[8][33];
    int aidx[32];
    float aflag[32];
    int cidx[128];
    float cflag[128];
    int pidx[64];
    float pflag[64];
    int nidx[64];
    float nflag[64];
    int cntA, cntN, coll, bstar;
    float bestv;
    int besti;
};

__device__ __forceinline__ void pair_argmax(PairSmem* S, float v, int i, int tid) {
    int lane = tid & 31, w = tid >> 5;
#pragma unroll
    for (int off = 16; off; off >>= 1) {
        float ov = __shfl_down_sync(0xffffffffu, v, off);
        int oi = __shfl_down_sync(0xffffffffu, i, off);
        if (ov > v || (ov == v && oi < i)) { v = ov; i = oi; }
    }
    if (lane == 0) { S->red[w] = v; S->redi[w] = i; }
    __syncthreads();
    if (w == 0) {
        v = (lane < 8) ? S->red[lane] : -FLT_MAX;
        i = (lane < 8) ? S->redi[lane] : 0x7FFFFFFF;
#pragma unroll
        for (int off = 4; off; off >>= 1) {
            float ov = __shfl_down_sync(0xffffffffu, v, off);
            int oi = __shfl_down_sync(0xffffffffu, i, off);
            if (ov > v || (ov == v && oi < i)) { v = ov; i = oi; }
        }
        if (lane == 0) { S->bestv = v; S->besti = i; }
    }
    __syncthreads();
}

__device__ void select_topk(PairSmem* S, const unsigned short* list, int cnt,
                            const float* __restrict__ key, int K, int* oidx, float* oflag,
                            int tid) {
    float lastv = FLT_MAX;
    int lasti = -1;
    for (int kk = 0; kk < K; kk++) {
        float bv = -FLT_MAX;
        int bi = 0x7FFFFFFF;
        for (int ii = tid; ii < cnt; ii += 256) {
            int idx = list[ii];
            float v = key[idx];
            if (v < lastv || (v == lastv && idx > lasti)) {
                if (v > bv || (v == bv && idx < bi)) { bv = v; bi = idx; }
            }
        }
        pair_argmax(S, bv, bi, tid);
        float gbv = S->bestv;
        int gbi = S->besti;
        if (gbv > -FLT_MAX) {
            lastv = gbv;
            lasti = gbi;
            if (tid == 0) { oidx[kk] = gbi; oflag[kk] = 1.f; }
        } else {
            lastv = -FLT_MAX;
            lasti = 0x7FFFFFFF;
            if (tid == 0) { oidx[kk] = 0; oflag[kk] = 0.f; }
        }
        __syncthreads();
    }
}

__device__ void bitonic_desc(PairSmem* S, int n, int tid) {
    for (int k = 2; k <= n; k <<= 1)
        for (int j = k >> 1; j > 0; j >>= 1) {
            for (int t = tid; t < n; t += 256) {
                int ixj = t ^ j;
                if (ixj > t) {
                    unsigned long long x = S->sbuf[t], y = S->sbuf[ixj];
                    bool desc = ((t & k) == 0);
                    if (desc ? (x < y) : (x > y)) {
                        S->sbuf[t] = y;
                        S->sbuf[ixj] = x;
                    }
                }
            }
            __syncthreads();
        }
}

__device__ void radix_select(PairSmem* S, const unsigned short* list, int cnt,
                             const float* __restrict__ key, int K, int* oidx, float* oflag,
                             int tid) {
    int target = min(K, cnt);
    if (target == 0) {
        for (int kk = tid; kk < K; kk += 256) { oidx[kk] = 0; oflag[kk] = 0.f; }
        __syncthreads();
        return;
    }
    S->hist[tid] = 0;
    __syncthreads();
    for (int ii = tid; ii < cnt; ii += 256) {
        float r = key[list[ii]];
        int b = (int)(r * 256.f);
        b = b < 0 ? 0 : (b > 255 ? 255 : b);
        atomicAdd(&S->hist[b], 1);
    }
    __syncthreads();
    if (tid == 0) {
        int acc = 0, bs = 0;
        for (int b = 255; b >= 0; b--) {
            acc += S->hist[b];
            if (acc >= target) { bs = b; break; }
        }
        S->bstar = bs;
        S->coll = 0;
    }
    __syncthreads();
    int bstar = S->bstar;
    for (int ii = tid; ii < cnt; ii += 256) {
        int idx = list[ii];
        float r = key[idx];
        int b = (int)(r * 256.f);
        b = b < 0 ? 0 : (b > 255 ? 255 : b);
        if (b >= bstar) {
            int p = atomicAdd(&S->coll, 1);
            if (p < 4096)
                S->sbuf[p] = ((unsigned long long)__float_as_uint(r) << 32) |
                             (unsigned long long)(unsigned int)(~(unsigned int)idx);
        }
    }
    __syncthreads();
    int coll = S->coll;
    if (coll > 4096) {
        select_topk(S, list, cnt, key, K, oidx, oflag, tid);
        return;
    }
    int n = 1;
    while (n < coll) n <<= 1;
    for (int i = coll + tid; i < n; i += 256) S->sbuf[i] = 0ull;
    __syncthreads();
    bitonic_desc(S, n, tid);
    for (int kk = tid; kk < K; kk += 256) {
        if (kk < target) {
            oidx[kk] = (int)(~(unsigned int)(S->sbuf[kk] & 0xFFFFFFFFull));
            oflag[kk] = 1.f;
        } else {
            oidx[kk] = 0;
            oflag[kk] = 0.f;
        }
    }
    __syncthreads();
}

__device__ void hard_select(PairSmem* S, const float* __restrict__ ub, int* oidx, float* oflag,
                            int tid) {
    if (tid < 128) {
        unsigned long long kv;
        if (S->cflag[tid] != 0.f) {
            unsigned int u = __float_as_uint(ub[S->cidx[tid]]) + 1u;
            kv = ((unsigned long long)u << 32) |
                 (unsigned long long)(unsigned int)(~(unsigned int)tid);
        } else {
            kv = (unsigned long long)(unsigned int)(~(unsigned int)tid);
        }
        S->sbuf[tid] = kv;
    }
    __syncthreads();
    bitonic_desc(S, 128, tid);
    if (tid < 64) {
        int t = (int)((~(unsigned int)(S->sbuf[tid] & 0xFFFFFFFFull)) & 127u);
        oidx[tid] = S->cidx[t];
        oflag[tid] = S->cflag[t];
    }
    __syncthreads();
}

__global__ __launch_bounds__(256) void k_pair(const float* __restrict__ unc,
                                              const float* __restrict__ r_anc,
                                              const float* __restrict__ r_pos,
                                              const float* __restrict__ r_neg) {
    extern __shared__ char smraw[];
    PairSmem* S = (PairSmem*)smraw;
    int task = blockIdx.x;
    int b = task >> 1, c = task & 1;
    int tid = threadIdx.x, w = tid >> 5, l = tid & 31;
    const unsigned char* am = (c == 0 ? g_m1 : g_m0) + b * HW;
    const unsigned char* nm = (c == 0 ? g_m0 : g_m1) + b * HW;

    if (tid == 0) { S->cntA = 0; S->cntN = 0; }
    __syncthreads();
    for (int i = tid; i < HW; i += 256) {
        if (am[i]) { int p = atomicAdd(&S->cntA, 1); S->listA[p] = (unsigned short)i; }
        if (nm[i]) { int p = atomicAdd(&S->cntN, 1); S->listN[p] = (unsigned short)i; }
    }
    __syncthreads();
    int cntA = S->cntA, cntN = S->cntN;

    const float* ra = r_anc + ((size_t)b * 2 + c) * HW;
    const float* rp = r_pos + ((size_t)b * 2 + c) * HW;
    const float* rn = r_neg + ((size_t)b * 2 + c) * HW;
    const float* ub = unc + (size_t)b * HW;

    radix_select(S, S->listA, cntA, ra, 32, S->aidx, S->aflag, tid);
    radix_select(S, S->listA, cntA, rp, 128, S->cidx, S->cflag, tid);
    hard_select(S, ub, S->pidx, S->pflag, tid);
    radix_select(S, S->listN, cntN, rn, 128, S->cidx, S->cflag, tid);
    hard_select(S, ub, S->nidx, S->nflag, tid);

    const float* projb = g_proj + (size_t)b * HW * 256;  // [n][e] coalesced rows

    for (int q = 0; q < 4; q++) {
        int a = w * 4 + q;
        const float* src = projb + (size_t)S->aidx[a] * 256;
        float v[8], ss = 0.f;
#pragma unroll
        for (int cc = 0; cc < 8; cc++) {
            v[cc] = src[l + 32 * cc];
            ss = fmaf(v[cc], v[cc], ss);
        }
#pragma unroll
        for (int off = 16; off; off >>= 1) ss += __shfl_xor_sync(0xffffffffu, ss, off);
        float sc = 1.f / fmaxf(sqrtf(ss), 1e-12f);
#pragma unroll
        for (int cc = 0; cc < 8; cc++) S->qs[a * 257 + l + 32 * cc] = v[cc] * sc;
    }
    __syncthreads();

    float accP = 0.f, accN = 0.f;
    for (int s = w; s < 128; s += 8) {
        int si = s & 63;
        bool isP = s < 64;
        float fl = isP ? S->pflag[si] : S->nflag[si];
        if (fl != 0.f) {
            int idx = isP ? S->pidx[si] : S->nidx[si];
            const float* src = projb + (size_t)idx * 256;
            float v[8], ss = 0.f;
#pragma unroll
            for (int cc = 0; cc < 8; cc++) {
                v[cc] = src[l + 32 * cc];
                ss = fmaf(v[cc], v[cc], ss);
            }
#pragma unroll
            for (int off = 16; off; off >>= 1) ss += __shfl_xor_sync(0xffffffffu, ss, off);
            float sc = 1.f / fmaxf(sqrtf(ss), 1e-12f);
#pragma unroll
            for (int cc = 0; cc < 8; cc++) S->vbuf[w][l + 32 * cc] = v[cc] * sc;
            __syncwarp();
            float dot = 0.f;
            const float* qrow = &S->qs[l * 257];
#pragma unroll 8
            for (int d = 0; d < 256; d++) dot = fmaf(qrow[d], S->vbuf[w][d], dot);
            float ev = expf(dot * 10.f);
            if (isP) accP += ev; else accN += ev;
            __syncwarp();
        }
    }
    S->warpP[w][l] = accP;
    S->warpN[w][l] = accN;
    __syncthreads();

    if (w == 0) {
        float p = 0.f, n = 0.f;
#pragma unroll
        for (int ww = 0; ww < 8; ww++) {
            p += S->warpP[ww][l];
            n += S->warpN[ww][l];
        }
        bool inc = (cntA >= 1) && (cntN >= 1);
        if (!inc) p += 1.f;
        float per = -logf(p / (p + n + 1e-8f));
        float af = S->aflag[l];
        float ws = per * af, as = af;
#pragma unroll
        for (int off = 16; off; off >>= 1) {
            ws += __shfl_down_sync(0xffffffffu, ws, off);
            as += __shfl_down_sync(0xffffffffu, as, off);
        }
        if (l == 0) {
            g_bl[task] = inc ? (ws / fmaxf(as, 1.f)) : 0.f;
            g_inc[task] = inc ? 1 : 0;
        }
    }
}

// ---------------- final: local + global loss ---------------------------------
__global__ __launch_bounds__(256) void k_final(float* __restrict__ out, int out_size) {
    __shared__ float scratch[34];
    __shared__ float qf[4][257], qb[4][257];
    __shared__ float cf[4], cb[4];
    __shared__ float pfv[4], pbv[4], nfv[4], nbv[4];
    int tid = threadIdx.x;

    for (int b = 0; b < 4; b++) {
        float c1 = 0.f, c0 = 0.f;
        for (int i = tid; i < HW; i += 256) {
            c1 += (float)g_m1[b * HW + i];
            c0 += (float)g_m0[b * HW + i];
        }
        float s1 = blk_sum(scratch, c1, tid);
        float s0 = blk_sum(scratch, c0, tid);
        if (tid == 0) { cf[b] = s1; cb[b] = s0; }
    }
    __syncthreads();

    for (int b = 0; b < 4; b++) {
        float mf = g_mfg[b * Dm + tid] / fmaxf(cf[b], 1.f);
        float mb_ = g_mbg[b * Dm + tid] / fmaxf(cb[b], 1.f);
        float ssf = blk_sum(scratch, mf * mf, tid);
        qf[b][tid] = mf / fmaxf(sqrtf(ssf), 1e-12f);
        float ssb = blk_sum(scratch, mb_ * mb_, tid);
        qb[b][tid] = mb_ / fmaxf(sqrtf(ssb), 1e-12f);
    }
    __syncthreads();

    for (int b = 0; b < 4; b++) {
        float d1 = blk_sum(scratch, qf[b][tid] * qf[b][tid], tid);
        float d2 = blk_sum(scratch, qb[b][tid] * qb[b][tid], tid);
        if (tid == 0) {
            pfv[b] = expf(d1 * 10.f);
            pbv[b] = expf(d2 * 10.f);
            nfv[b] = 0.f;
            nbv[b] = 0.f;
        }
        __syncthreads();
    }
    for (int b = 0; b < 4; b++) {
        for (int j = 0; j <= b; j++) {
            float dqbqf = blk_sum(scratch, qb[j][tid] * qf[b][tid], tid);
            float dqfqb = blk_sum(scratch, qf[j][tid] * qb[b][tid], tid);
            if (tid == 0) {
                bool vgj = (cf[j] >= 1.f) && (cb[j] >= 1.f);
                if (vgj) {
                    nfv[b] += expf(dqbqf * 10.f);
                    nbv[b] += expf(dqfqb * 10.f);
                }
            }
            __syncthreads();
        }
    }

    if (tid == 0) {
        float lsum = 0.f;
        int icnt = 0;
        for (int t = 0; t < 8; t++) {
            lsum += g_bl[t];
            icnt += g_inc[t];
        }
        float l_local = lsum / (float)max(icnt, 1);
        float gs = 0.f;
        int vcnt = 0;
        for (int b = 0; b < 4; b++) {
            bool vg = (cf[b] >= 1.f) && (cb[b] >= 1.f);
            if (vg) {
                float lg = -logf(pfv[b] / (pfv[b] + nfv[b] + 1e-8f)) -
                           logf(pbv[b] / (pbv[b] + nbv[b] + 1e-8f));
                gs += lg;
                vcnt++;
            }
        }
        float l_global = gs / (float)max(vcnt, 1);
        if (out_size > 0) out[0] = l_local + 0.5f * l_global;
        if (out_size > 1) out[1] = l_local;
        if (out_size > 2) out[2] = l_global;
    }
}

// ---------------- launch ------------------------------------------------------
extern "C" void kernel_launch(void* const* d_in, const int* in_sizes, int n_in, void* d_out,
                              int out_size) {
    const float* feat = (const float*)d_in[0];
    const int* labels = (const int*)d_in[1];
    const float* prob_ori = (const float*)d_in[2];
    const float* prob_aug = (const float*)d_in[3];
    const float* unc = (const float*)d_in[4];
    const float* r_anc = (const float*)d_in[5];
    const float* r_pos = (const float*)d_in[6];
    const float* r_neg = (const float*)d_in[7];
    const float* w1 = (const float*)d_in[8];
    const float* b1 = (const float*)d_in[9];
    const float* gamma = (const float*)d_in[10];
    const float* beta = (const float*)d_in[11];
    const float* w2 = (const float*)d_in[12];
    const float* b2 = (const float*)d_in[13];

    cudaFuncSetAttribute(k_gemm_mma<false>, cudaFuncAttributeMaxDynamicSharedMemorySize,
                         GEMM_SMEM);
    cudaFuncSetAttribute(k_gemm_mma<true>, cudaFuncAttributeMaxDynamicSharedMemorySize,
                         GEMM_SMEM);
    cudaFuncSetAttribute(k_pair, cudaFuncAttributeMaxDynamicSharedMemorySize,
                         (int)sizeof(PairSmem));

    k_masks<<<(Bm * HW + 255) / 256, 256>>>(prob_ori, prob_aug, unc, labels);
    dim3 gg(NBLK, 2, Bm);
    k_gemm_mma<false><<<gg, 256, GEMM_SMEM>>>(feat, w1, b1);
    k_finstats<<<Dm, 128>>>(gamma, beta);
    k_gemm_mma<true><<<gg, 256, GEMM_SMEM>>>(nullptr, w2, b2);
    k_finproto<<<dim3(Dm, Bm), 128>>>();
    k_pair<<<8, 256, sizeof(PairSmem)>>>(unc, r_anc, r_pos, r_neg);
    k_final<<<1, 256>>>((float*)d_out, out_size);
}